// round 16
// baseline (speedup 1.0000x reference)
#include <cuda_runtime.h>
#include <cuda_bf16.h>
#include <math.h>
#include <stdint.h>

#define T_STEPS 400
#define BATCH   256
#define NH      512
#define NCTA    128
#define NTHR    544                   // 16 compute warps + 1 producer warp
#define TOT_CHUNKS (T_STEPS*40)

// ---- tile images ----
#define A_IMG   17408                 // 32 rows x 272B (hi 8704) + lo 8704
#define A_HALF  8704
#define B_IMG   36864                 // 128 rows x 144B (hi 18432) + lo 18432
#define B_HALF  18432

// ---- smem layout (bytes) ----
#define SM_B0   0                     // 3 rotating B slots (full/empty mbar piped)
#define SM_A    110592                // 4 chunk positions = one level's A (69632)
#define SM_RED  180224                // 4 x 8704 partials (2-stage: kh<4 write, kh>=4 RMW)
#define SM_BAR  215040                // Bf[3], Be[3], AF[4], AE
#define SM_TOTAL 215168

#define BAR_BF(s) (SM_BAR + (s)*8)
#define BAR_BE(s) (SM_BAR + 24 + (s)*8)
#define BAR_AF(c) (SM_BAR + 48 + (c)*8)
#define BAR_AE    (SM_BAR + 80)

// compute-warp-only barrier (producer warp never joins)
#define CSYNC() asm volatile("bar.sync 1, 512;" ::: "memory")

// ---- persistent device buffers (no cudaMalloc allowed) ----
__device__ __align__(16) char g_Bpk[640ull*B_IMG];          // 40 sched-slots x 16 jb
__device__ __align__(16) char g_st [6ull*8*4*A_IMG];        // states s0,s1,s2,s3,s5,h : [st][rb][chunk]
__device__ __align__(16) char g_xpk[(size_t)T_STEPS*8*4*A_IMG];  // prepacked x images [t][rb][chunk]
__device__ unsigned long long g_barr[8*32];                 // rb-local event counters (monotonic)
__device__ unsigned long long g_base[8];                    // per-launch baselines (set by prepack)

// ---- asm helpers ----
__device__ __forceinline__ uint32_t smem_u32(const void* p) {
    uint32_t a;
    asm("{ .reg .u64 t; cvta.to.shared.u64 t, %1; cvt.u32.u64 %0, t; }" : "=r"(a) : "l"(p));
    return a;
}
#define LDM4(r, a) \
    asm volatile("ldmatrix.sync.aligned.m8n8.x4.shared.b16 {%0,%1,%2,%3}, [%4];" \
        : "=r"((r)[0]), "=r"((r)[1]), "=r"((r)[2]), "=r"((r)[3]) : "r"(a))
#define LDM4T(r, a) \
    asm volatile("ldmatrix.sync.aligned.m8n8.x4.trans.shared.b16 {%0,%1,%2,%3}, [%4];" \
        : "=r"((r)[0]), "=r"((r)[1]), "=r"((r)[2]), "=r"((r)[3]) : "r"(a))
#define MMAB(d, a, b0, b1) \
    asm volatile("mma.sync.aligned.m16n8k16.row.col.f32.bf16.bf16.f32 " \
        "{%0,%1,%2,%3},{%4,%5,%6,%7},{%8,%9},{%0,%1,%2,%3};" \
        : "+f"((d)[0]), "+f"((d)[1]), "+f"((d)[2]), "+f"((d)[3]) \
        : "r"((a)[0]), "r"((a)[1]), "r"((a)[2]), "r"((a)[3]), "r"(b0), "r"(b1))
#define MBAR_ARRIVE(bar) \
    asm volatile("mbarrier.arrive.shared.b64 _, [%0];" :: "r"(bar) : "memory")

__device__ __forceinline__ void mbar_init(uint32_t bar, uint32_t cnt) {
    asm volatile("mbarrier.init.shared.b64 [%0], %1;" :: "r"(bar), "r"(cnt) : "memory");
}
__device__ __forceinline__ void mbar_wait(uint32_t bar, uint32_t parity) {
    asm volatile(
        "{\n\t.reg .pred P;\n\tWL_%=:\n\t"
        "mbarrier.try_wait.parity.acquire.cta.shared::cta.b64 P, [%0], %1;\n\t"
        "@P bra.uni WD_%=;\n\tbra.uni WL_%=;\n\tWD_%=:\n\t}"
        :: "r"(bar), "r"(parity) : "memory");
}
__device__ __forceinline__ void bulk_g2s(uint32_t dst, const void* src, uint32_t bytes, uint32_t bar) {
    asm volatile("mbarrier.arrive.expect_tx.shared.b64 _, [%0], %1;" :: "r"(bar), "r"(bytes) : "memory");
    asm volatile("cp.async.bulk.shared::cta.global.mbarrier::complete_tx::bytes [%0], [%1], %2, [%3];"
                 :: "r"(dst), "l"(src), "r"(bytes), "r"(bar) : "memory");
}

// Arrive-only cross-CTA event: publish this CTA's state stores. NO wait.
__device__ __forceinline__ void arrive_event(int rb, int tid) {
    CSYNC();
    if (tid == 0) { __threadfence(); atomicAdd(&g_barr[rb * 32], 1ULL); }
}

__device__ __forceinline__ float sigf(float x) { return 1.0f / (1.0f + expf(-x)); }
__device__ __forceinline__ uint32_t pack_bf16x2(float a, float b) {
    __nv_bfloat16 ba = __float2bfloat16(a), bb = __float2bfloat16(b);
    return ((uint32_t)__bfloat16_as_ushort(bb) << 16) | __bfloat16_as_ushort(ba);
}
__device__ __forceinline__ float bf16lo(uint32_t w) {
    return __bfloat162float(__ushort_as_bfloat16((unsigned short)(w & 0xffff)));
}
__device__ __forceinline__ float bf16hi(uint32_t w) {
    return __bfloat162float(__ushort_as_bfloat16((unsigned short)(w >> 16)));
}

// ---- producer-side primitives (warp 16 lane 0 only) ----
__device__ __forceinline__ void issue_B(int q, int jb, uint32_t smu) {
    if (q >= TOT_CHUNKS) return;
    mbar_wait(smu + BAR_BE(q % 3), (uint32_t)(((q / 3) & 1) ^ 1));
    bulk_g2s(smu + SM_B0 + (q % 3) * B_IMG,
             g_Bpk + ((size_t)((q % 40) * 16 + jb)) * B_IMG, B_IMG, smu + BAR_BF(q % 3));
}
__device__ __forceinline__ void a_bulk4(const char* src, uint32_t smu, int k) {
    mbar_wait(smu + BAR_AE, (uint32_t)((k & 1) ^ 1));
    asm volatile("fence.proxy.async.shared::cta;" ::: "memory");
    #pragma unroll
    for (int c = 0; c < 4; ++c)
        bulk_g2s(smu + SM_A + c * A_IMG, src + (size_t)c * A_IMG, A_IMG, smu + BAR_AF(c));
}
__device__ __forceinline__ void epoch_wait(unsigned long long* ctr, unsigned long long need) {
    while (*(volatile unsigned long long*)ctr < need) { __nanosleep(32); }
    __threadfence();
}

// One K=128 chunk of HMMA. Warp (kh,nw): ks = kh (1 of 8); 32 cols:
// c-cols [nw*16, +16) and h-cols [32+nw*16, +16) of the 64-col tile.
__device__ __forceinline__ void mma_chunk(uint32_t smu, int slot, int abuf_off,
                                          int lane, int kh, int nw, float acc[2][4][4]) {
    uint32_t Bb = smu + SM_B0 + slot * B_IMG;
    uint32_t Ab = smu + SM_A + abuf_off;
    int l15 = lane & 15, l16 = lane >> 4;
    int ks = kh;
    uint32_t ah[2][4], al[2][4], bh[2][4], bl[2][4];
    uint32_t kb = (uint32_t)(ks * 16 + l16 * 8) * 2;
    #pragma unroll
    for (int mf = 0; mf < 2; ++mf) {
        uint32_t aa = Ab + (uint32_t)(mf * 16 + l15) * 272 + kb;
        LDM4(ah[mf], aa);
        LDM4(al[mf], aa + A_HALF);
    }
    #pragma unroll
    for (int l = 0; l < 2; ++l) {
        uint32_t ba = Bb + (uint32_t)(ks * 16 + l15) * 144
                    + (uint32_t)(nw * 64 + l * 32 + l16 * 16);
        LDM4T(bh[l], ba);
        LDM4T(bl[l], ba + B_HALF);
    }
    #pragma unroll
    for (int mf = 0; mf < 2; ++mf)
        #pragma unroll
        for (int l = 0; l < 2; ++l) {
            MMAB(acc[mf][l*2+0], ah[mf], bh[l][0], bh[l][1]);
            MMAB(acc[mf][l*2+0], ah[mf], bl[l][0], bl[l][1]);
            MMAB(acc[mf][l*2+0], al[mf], bh[l][0], bh[l][1]);
            MMAB(acc[mf][l*2+1], ah[mf], bh[l][2], bh[l][3]);
            MMAB(acc[mf][l*2+1], ah[mf], bl[l][2], bl[l][3]);
            MMAB(acc[mf][l*2+1], al[mf], bh[l][2], bh[l][3]);
        }
}

// 4 chunks, consumer side only: [AF wait] -> Bf wait -> mma -> Be arrive.
__device__ __forceinline__ void chunks4(uint32_t smu, int lane, int kh, int nw,
                                        int& n, float acc[2][4][4],
                                        bool af, uint32_t afp) {
    #pragma unroll
    for (int c = 0; c < 4; ++c) {
        if (af) mbar_wait(smu + BAR_AF(c), afp);
        mbar_wait(smu + BAR_BF(n % 3), (uint32_t)((n / 3) & 1));
        mma_chunk(smu, n % 3, c * A_IMG, lane, kh, nw, acc);
        if (lane == 0) MBAR_ARRIVE(smu + BAR_BE(n % 3));
        ++n;
    }
}
#define ZERO_ACC(acc) { _Pragma("unroll") for (int _m = 0; _m < 2; ++_m) \
    _Pragma("unroll") for (int _f = 0; _f < 4; ++_f) \
    _Pragma("unroll") for (int _e = 0; _e < 4; ++_e) (acc)[_m][_f][_e] = 0.f; }

// 2-stage k-reduction over 8 partials in 4 buffers, gate, store packed state.
// Stage 1: kh<4 write red[kh]. Stage 2: kh>=4 RMW-add into red[kh-4]. Readers see 4 buffers.
__device__ void red_epilogue(char* sm, uint32_t smu, const float acc[2][4][4], int lane,
                             int kh, int nw, char* dst_pk, int act, bool do_mean,
                             float mean[2], int er, int ej, bool arrive_ae) {
    const char* spp = sm + SM_A + (ej >> 7) * A_IMG + er * 272 + (ej & 127) * 2;
    uint32_t hiw = *(const uint32_t*)spp;
    uint32_t low = *(const uint32_t*)(spp + A_HALF);
    float sp0 = bf16lo(hiw) + bf16lo(low);
    float sp1 = bf16hi(hiw) + bf16hi(low);
    if (arrive_ae) {
        __syncwarp();
        if (lane == 0) MBAR_ARRIVE(smu + BAR_AE);
    }
    CSYNC();                                           // all mma done; prior red reads done
    float* red = (float*)(sm + SM_RED) + (kh & 3) * 2176;   // 32 x 68
    int g = lane >> 2, t4 = lane & 3;
    if (kh < 4) {
        #pragma unroll
        for (int mf = 0; mf < 2; ++mf)
            #pragma unroll
            for (int q = 0; q < 4; ++q) {
                int row = mf * 16 + g;
                int col = (q & 1) * 32 + nw * 16 + (q >> 1) * 8 + t4 * 2;
                *(float2*)(red + row * 68 + col)       = make_float2(acc[mf][q][0], acc[mf][q][1]);
                *(float2*)(red + (row + 8) * 68 + col) = make_float2(acc[mf][q][2], acc[mf][q][3]);
            }
    }
    CSYNC();
    if (kh >= 4) {
        #pragma unroll
        for (int mf = 0; mf < 2; ++mf)
            #pragma unroll
            for (int q = 0; q < 4; ++q) {
                int row = mf * 16 + g;
                int col = (q & 1) * 32 + nw * 16 + (q >> 1) * 8 + t4 * 2;
                float2 v0 = *(float2*)(red + row * 68 + col);
                float2 v1 = *(float2*)(red + (row + 8) * 68 + col);
                v0.x += acc[mf][q][0]; v0.y += acc[mf][q][1];
                v1.x += acc[mf][q][2]; v1.y += acc[mf][q][3];
                *(float2*)(red + row * 68 + col)       = v0;
                *(float2*)(red + (row + 8) * 68 + col) = v1;
            }
    }
    CSYNC();
    int lj = ej & 31;
    float c0 = 0.f, c1 = 0.f, h0 = 0.f, h1 = 0.f;
    #pragma unroll
    for (int p = 0; p < 4; ++p) {
        const float* r = (const float*)(sm + SM_RED) + p * 2176 + er * 68;
        float2 pc = *(const float2*)(r + lj);
        float2 ph = *(const float2*)(r + 32 + lj);
        c0 += pc.x; c1 += pc.y; h0 += ph.x; h1 += ph.y;
    }
    float hv0 = (act == 0) ? tanhf(h0) : (act == 1) ? fmaxf(h0, 0.f) : (act == 2) ? sigf(h0) : h0;
    float hv1 = (act == 0) ? tanhf(h1) : (act == 1) ? fmaxf(h1, 0.f) : (act == 2) ? sigf(h1) : h1;
    float s0 = sp0 + sigf(c0) * (hv0 - sp0);
    float s1 = sp1 + sigf(c1) * (hv1 - sp1);
    if (do_mean) { mean[0] += s0; mean[1] += s1; }
    if (dst_pk) {
        __nv_bfloat16 b0 = __float2bfloat16(s0), b1 = __float2bfloat16(s1);
        uint32_t hw = ((uint32_t)__bfloat16_as_ushort(b1) << 16) | __bfloat16_as_ushort(b0);
        uint32_t lw = pack_bf16x2(s0 - __bfloat162float(b0), s1 - __bfloat162float(b1));
        char* dp = dst_pk + (ej >> 7) * A_IMG + er * 272 + (ej & 127) * 2;
        *(uint32_t*)dp = hw;
        *(uint32_t*)(dp + A_HALF) = lw;
    }
}

// ---- prepass: pack weights/h0/x; snapshot event-counter baselines ----
__global__ void prepack_kernel(const float* __restrict__ W0, const float* __restrict__ Ws,
                               const float* __restrict__ hidden0, const float* __restrict__ inputs) {
    if (blockIdx.x == 0 && threadIdx.x < 8)
        g_base[threadIdx.x] = g_barr[threadIdx.x * 32];
    const int lvl_order[8] = {0, 1, 2, 3, 4, 6, 5, 7};
    const int W_ITEMS = 640 * 1024;
    const int H_ITEMS = 65536;
    const int X_ITEMS = T_STEPS * 256 * 128;
    const int TOTAL = W_ITEMS + H_ITEMS + X_ITEMS;
    for (int idx = blockIdx.x * blockDim.x + threadIdx.x; idx < TOTAL; idx += gridDim.x * blockDim.x) {
        if (idx < W_ITEMS) {
            int g8 = idx & 7;
            int kr = (idx >> 3) & 127;
            int tt = idx >> 10;
            int sp = tt >> 4, jb = tt & 15;
            const float* src; int kbase;
            if (sp < 8) { src = W0; kbase = sp * 128; }
            else { int sp2 = sp - 8; src = Ws + (size_t)lvl_order[sp2 >> 2] * 512 * 1024; kbase = (sp2 & 3) * 128; }
            __align__(16) __nv_bfloat16 hb[8], lb[8];
            #pragma unroll
            for (int e = 0; e < 8; ++e) {
                int cidx = g8 * 8 + e;
                int nw2 = cidx >> 4, w16 = cidx & 15;
                int gc = (w16 < 8) ? (jb * 32 + nw2 * 8 + w16)
                                   : (512 + jb * 32 + nw2 * 8 + (w16 - 8));
                float wv = src[(size_t)(kbase + kr) * 1024 + gc];
                __nv_bfloat16 h = __float2bfloat16(wv);
                hb[e] = h;
                lb[e] = __float2bfloat16(wv - __bfloat162float(h));
            }
            size_t boff = (size_t)tt * B_IMG + kr * 144 + g8 * 16;
            *(uint4*)(g_Bpk + boff)          = *(const uint4*)hb;
            *(uint4*)(g_Bpk + boff + B_HALF) = *(const uint4*)lb;
        } else if (idx < W_ITEMS + H_ITEMS) {
            int i2 = idx - W_ITEMS;
            int row = i2 >> 8, col = (i2 & 255) * 2;
            float v0 = hidden0[(size_t)row * NH + col];
            float v1 = hidden0[(size_t)row * NH + col + 1];
            __nv_bfloat16 b0 = __float2bfloat16(v0), b1 = __float2bfloat16(v1);
            uint32_t hw = ((uint32_t)__bfloat16_as_ushort(b1) << 16) | __bfloat16_as_ushort(b0);
            uint32_t lw = pack_bf16x2(v0 - __bfloat162float(b0), v1 - __bfloat162float(b1));
            char* dp = g_st + ((size_t)(5 * 8 + (row >> 5)) * 4 + (col >> 7)) * A_IMG
                     + (row & 31) * 272 + (col & 127) * 2;
            *(uint32_t*)dp = hw;
            *(uint32_t*)(dp + A_HALF) = lw;
        } else {
            int i3 = idx - W_ITEMS - H_ITEMS;
            int g  = i3 & 127;
            int row = (i3 >> 7) & 255;
            int t   = i3 >> 15;
            int ch = g >> 5, k4 = g & 31;
            float4 v = *(const float4*)(inputs + ((size_t)t * BATCH + row) * NH + g * 4);
            __nv_bfloat16 h0 = __float2bfloat16(v.x), h1 = __float2bfloat16(v.y),
                          h2 = __float2bfloat16(v.z), h3 = __float2bfloat16(v.w);
            uint32_t ph0 = ((uint32_t)__bfloat16_as_ushort(h1) << 16) | __bfloat16_as_ushort(h0);
            uint32_t ph1 = ((uint32_t)__bfloat16_as_ushort(h3) << 16) | __bfloat16_as_ushort(h2);
            uint32_t pl0 = pack_bf16x2(v.x - __bfloat162float(h0), v.y - __bfloat162float(h1));
            uint32_t pl1 = pack_bf16x2(v.z - __bfloat162float(h2), v.w - __bfloat162float(h3));
            char* ab = g_xpk + ((size_t)((size_t)t * 8 + (row >> 5)) * 4 + ch) * A_IMG
                     + (row & 31) * 272 + k4 * 8;
            *(uint2*)ab            = make_uint2(ph0, ph1);
            *(uint2*)(ab + A_HALF) = make_uint2(pl0, pl1);
        }
    }
}

__global__ void __launch_bounds__(NTHR, 1)
rnn_kernel(float* __restrict__ out) {
    extern __shared__ char sm[];
    uint32_t smu = smem_u32(sm);
    int tid = threadIdx.x, lane = tid & 31, warp = tid >> 5;
    int rb = blockIdx.x >> 4, jb = blockIdx.x & 15;
    int colc = jb * 32;

    char* P[6];
    #pragma unroll
    for (int s = 0; s < 6; ++s) P[s] = g_st + ((size_t)(s * 8 + rb) * 4) * A_IMG;

    if (tid == 0) {
        #pragma unroll
        for (int s = 0; s < 3; ++s) { mbar_init(smu + BAR_BF(s), 1); mbar_init(smu + BAR_BE(s), 16); }
        #pragma unroll
        for (int c = 0; c < 4; ++c) mbar_init(smu + BAR_AF(c), 1);
        mbar_init(smu + BAR_AE, 16);
    }
    __syncthreads();   // full block (incl. producer warp) — once, before divergence

    if (warp == 16) {
        // ---------------- producer warp (lane 0) ----------------
        if (lane == 0) {
            unsigned long long* ctr = &g_barr[rb * 32];
            unsigned long long B = g_base[rb];
            int n = 0, k = 0;
            issue_B(0, jb, smu); issue_B(1, jb, smu);
            a_bulk4(g_xpk + ((size_t)rb * 4) * A_IMG, smu, k); ++k;       // x(0)
            for (int t = 0; t < T_STEPS; ++t) {
                unsigned long long e = B + 80ull * t;
                for (int c = 0; c < 4; ++c) { issue_B(n + 2, jb, smu); ++n; }   // wave1 B
                epoch_wait(ctr, e);                                              // E5(t-1): h(t)
                a_bulk4(P[5], smu, k); ++k;
                for (int c = 0; c < 4; ++c) { issue_B(n + 2, jb, smu); ++n; }   // wave2 B
                epoch_wait(ctr, e + 16);                                         // E1: s0
                a_bulk4(P[0], smu, k); ++k;
                for (int c = 0; c < 4; ++c) { issue_B(n + 2, jb, smu); ++n; }   // n1 B
                epoch_wait(ctr, e + 32);                                         // E2: s1
                a_bulk4(P[1], smu, k); ++k;
                for (int c = 0; c < 12; ++c) { issue_B(n + 2, jb, smu); ++n; }  // n2,n3,n4 B
                epoch_wait(ctr, e + 48);                                         // E3: s2,s3
                a_bulk4(P[2], smu, k); ++k;
                for (int c = 0; c < 4; ++c) { issue_B(n + 2, jb, smu); ++n; }   // n5 B
                a_bulk4(P[3], smu, k); ++k;
                for (int c = 0; c < 4; ++c) { issue_B(n + 2, jb, smu); ++n; }   // n7 B
                epoch_wait(ctr, e + 64);                                         // E4: s5
                a_bulk4(P[4], smu, k); ++k;
                for (int c = 0; c < 8; ++c) { issue_B(n + 2, jb, smu); ++n; }   // n6,n8 B
                if (t + 1 < T_STEPS) {
                    a_bulk4(g_xpk + ((size_t)((size_t)(t + 1) * 8 + rb) * 4) * A_IMG, smu, k); ++k;
                }
            }
        }
        return;
    }

    // ---------------- compute warps (0..15, tid < 512) ----------------
    int kh = warp >> 1, nw = warp & 1;                  // 8 k-steps x 2 n-halves
    int er = tid >> 4;
    int ej = colc + (tid & 15) * 2;
    int grow = rb * 32 + er;

    int n = 0, naf = 1;
    float acc[2][4][4];
    for (int t = 0; t < T_STEPS; ++t) {
        float mean[2] = {0.f, 0.f};

        // ---- L0 wave1: x chunks ----
        ZERO_ACC(acc);
        chunks4(smu, lane, kh, nw, n, acc, true, (uint32_t)((naf - 1) & 1));
        if (lane == 0) MBAR_ARRIVE(smu + BAR_AE);      // release x region
        // ---- L0 wave2: h chunks ----
        ++naf;
        chunks4(smu, lane, kh, nw, n, acc, true, (uint32_t)((naf - 1) & 1));
        red_epilogue(sm, smu, acc, lane, kh, nw, P[0], 0, false, mean, er, ej, true);
        arrive_event(rb, tid);                          // E1: s0 published

        // ---- n1 = gate(s0 @ Ws0, tanh) ----
        ++naf;
        ZERO_ACC(acc);
        chunks4(smu, lane, kh, nw, n, acc, true, (uint32_t)((naf - 1) & 1));
        red_epilogue(sm, smu, acc, lane, kh, nw, P[1], 0, true, mean, er, ej, true);
        arrive_event(rb, tid);                          // E2: s1 published

        // ---- n2,n3,n4 (pred s1, A reused) ----
        ++naf;
        ZERO_ACC(acc);
        chunks4(smu, lane, kh, nw, n, acc, true, (uint32_t)((naf - 1) & 1));
        red_epilogue(sm, smu, acc, lane, kh, nw, P[2], 1, true, mean, er, ej, false);
        ZERO_ACC(acc);
        chunks4(smu, lane, kh, nw, n, acc, false, 0);
        red_epilogue(sm, smu, acc, lane, kh, nw, P[3], 1, true, mean, er, ej, false);
        arrive_event(rb, tid);                          // E3: s2,s3 published (before n4!)
        ZERO_ACC(acc);
        chunks4(smu, lane, kh, nw, n, acc, false, 0);
        red_epilogue(sm, smu, acc, lane, kh, nw, (char*)0, 3, true, mean, er, ej, true);

        // ---- n5 = gate(s2 @ Ws4, tanh) ----
        ++naf;
        ZERO_ACC(acc);
        chunks4(smu, lane, kh, nw, n, acc, true, (uint32_t)((naf - 1) & 1));
        red_epilogue(sm, smu, acc, lane, kh, nw, P[4], 0, true, mean, er, ej, true);
        arrive_event(rb, tid);                          // E4: s5 published (before n7!)
        // ---- n7 = gate(s3 @ Ws6, tanh) ----
        ++naf;
        ZERO_ACC(acc);
        chunks4(smu, lane, kh, nw, n, acc, true, (uint32_t)((naf - 1) & 1));
        red_epilogue(sm, smu, acc, lane, kh, nw, (char*)0, 0, true, mean, er, ej, true);

        // ---- n6 = gate(s5 @ Ws5, sigmoid); n8 = gate(s5 @ Ws7, relu) (A reused) ----
        ++naf;
        ZERO_ACC(acc);
        chunks4(smu, lane, kh, nw, n, acc, true, (uint32_t)((naf - 1) & 1));
        red_epilogue(sm, smu, acc, lane, kh, nw, (char*)0, 2, true, mean, er, ej, false);
        ZERO_ACC(acc);
        chunks4(smu, lane, kh, nw, n, acc, false, 0);
        red_epilogue(sm, smu, acc, lane, kh, nw, (char*)0, 1, true, mean, er, ej, true);

        if (t + 1 < T_STEPS) ++naf;                    // producer's x(t+1) bulks

        // ---- finalize: h = mean(states 1..8); packed h + fp32 out ----
        {
            float hv0 = mean[0] * 0.125f, hv1 = mean[1] * 0.125f;
            __nv_bfloat16 b0 = __float2bfloat16(hv0), b1 = __float2bfloat16(hv1);
            uint32_t hw = ((uint32_t)__bfloat16_as_ushort(b1) << 16) | __bfloat16_as_ushort(b0);
            uint32_t lw = pack_bf16x2(hv0 - __bfloat162float(b0), hv1 - __bfloat162float(b1));
            char* dp = P[5] + (ej >> 7) * A_IMG + er * 272 + (ej & 127) * 2;
            *(uint32_t*)dp = hw;
            *(uint32_t*)(dp + A_HALF) = lw;
            *(float2*)(out + ((size_t)t * BATCH + grow) * NH + ej) = make_float2(hv0, hv1);
            if (t == T_STEPS - 1)
                *(float2*)(out + (size_t)T_STEPS * BATCH * NH + (size_t)grow * NH + ej) = make_float2(hv0, hv1);
        }
        arrive_event(rb, tid);                          // E5: h published
    }
}

extern "C" void kernel_launch(void* const* d_in, const int* in_sizes, int n_in,
                              void* d_out, int out_size) {
    const float* inputs = (const float*)d_in[0];
    const float* hidden = (const float*)d_in[1];
    const float* W0     = (const float*)d_in[2];
    const float* Ws     = (const float*)d_in[3];
    float* out = (float*)d_out;

    prepack_kernel<<<1024, 1024>>>(W0, Ws, hidden, inputs);
    cudaFuncSetAttribute(rnn_kernel, cudaFuncAttributeMaxDynamicSharedMemorySize, SM_TOTAL);
    rnn_kernel<<<NCTA, NTHR, SM_TOTAL>>>(out);
}